// round 1
// baseline (speedup 1.0000x reference)
#include <cuda_runtime.h>
#include <cuda_bf16.h>

// Problem: B=512, H=8, C=8192
//   loss = sum_{b,h} lam[h] * mean_c bce(y_pred[b,c]*La[h,c], y_true[b,c]*La[h,c])
// Since La is 0/1 and masked entries contribute exactly 0 (torch log clamp at -100),
//   loss = sum_{b,c} bce(y_pred[b,c], y_true[b,c]) * w[c]
//   w[c]  = (1/C) * sum_h lam[h] * La[h,c]
//
// Inputs (metadata order): y_pred [B*C] f32, y_true [B*C] f32, La [H*C] f32, lam [H] f32
// Output: scalar f32.

#define B_DIM 512
#define H_DIM 8
#define C_DIM 8192
#define N_ELEM (B_DIM * C_DIM)      // 4194304
#define N4 (N_ELEM / 4)             // 1048576
#define C4 (C_DIM / 4)              // 2048

__device__ float g_w4[C_DIM];       // per-class weight, read as float4

// ---------------------------------------------------------------------------
// Kernel A: w[c] = (1/C) * sum_h lam[h]*La[h,c]; also zero the output scalar.
// ---------------------------------------------------------------------------
__global__ void multibce_weights_kernel(const float* __restrict__ La,
                                        const float* __restrict__ lam,
                                        float* __restrict__ out) {
    int c = blockIdx.x * blockDim.x + threadIdx.x;
    if (c < C_DIM) {
        float s = 0.0f;
#pragma unroll
        for (int h = 0; h < H_DIM; ++h) {
            s = fmaf(lam[h], La[h * C_DIM + c], s);
        }
        g_w4[c] = s * (1.0f / (float)C_DIM);
    }
    if (c == 0) out[0] = 0.0f;
}

// ---------------------------------------------------------------------------
// Kernel B: weighted BCE reduction over B*C elements.
// ---------------------------------------------------------------------------
__device__ __forceinline__ float bce1(float p, float t) {
    // -( t*max(log p, -100) + (1-t)*max(log(1-p), -100) )
    float lp  = fmaxf(__logf(p),        -100.0f);
    float l1p = fmaxf(__logf(1.0f - p), -100.0f);
    // = -( l1p + t*(lp - l1p) )
    return -fmaf(t, lp - l1p, l1p);
}

__global__ void __launch_bounds__(256)
multibce_reduce_kernel(const float4* __restrict__ yp,
                       const float4* __restrict__ yt,
                       float* __restrict__ out) {
    float acc = 0.0f;
    const float4* w4 = reinterpret_cast<const float4*>(g_w4);

    for (int i = blockIdx.x * blockDim.x + threadIdx.x; i < N4;
         i += gridDim.x * blockDim.x) {
        float4 p = yp[i];
        float4 t = yt[i];
        float4 w = w4[i & (C4 - 1)];
        acc = fmaf(w.x, bce1(p.x, t.x), acc);
        acc = fmaf(w.y, bce1(p.y, t.y), acc);
        acc = fmaf(w.z, bce1(p.z, t.z), acc);
        acc = fmaf(w.w, bce1(p.w, t.w), acc);
    }

    // warp reduce
#pragma unroll
    for (int o = 16; o > 0; o >>= 1)
        acc += __shfl_xor_sync(0xFFFFFFFFu, acc, o);

    // block reduce
    __shared__ float smem[8];
    int lane = threadIdx.x & 31;
    int warp = threadIdx.x >> 5;
    if (lane == 0) smem[warp] = acc;
    __syncthreads();
    if (warp == 0) {
        acc = (lane < (blockDim.x >> 5)) ? smem[lane] : 0.0f;
#pragma unroll
        for (int o = 4; o > 0; o >>= 1)
            acc += __shfl_xor_sync(0xFFFFFFFFu, acc, o);
        if (lane == 0) atomicAdd(out, acc);
    }
}

// ---------------------------------------------------------------------------
extern "C" void kernel_launch(void* const* d_in, const int* in_sizes, int n_in,
                              void* d_out, int out_size) {
    const float* y_pred = (const float*)d_in[0];
    const float* y_true = (const float*)d_in[1];
    const float* La     = (const float*)d_in[2];
    const float* lam    = (const float*)d_in[3];
    float* out = (float*)d_out;

    multibce_weights_kernel<<<(C_DIM + 255) / 256, 256>>>(La, lam, out);

    // 148 SMs * 8 blocks of 256 threads; grid-stride covers N4.
    multibce_reduce_kernel<<<1184, 256>>>(
        (const float4*)y_pred, (const float4*)y_true, out);
}

// round 3
// speedup vs baseline: 1.1604x; 1.1604x over previous
#include <cuda_runtime.h>
#include <cuda_bf16.h>

// Problem: B=512, H=8, C=8192
//   loss = sum_{b,c} bce(y_pred[b,c], y_true[b,c]) * w[c]
//   w[c]  = (1/C) * sum_h lam[h] * La[h,c]     (La binary => masked terms are 0)
// y_true is exactly binary, so
//   bce(p,t) = -max(log(t ? p : 1-p), -100)
//            = -ln2 * max(lg2(x), -100/ln2),  x = fma(p, 2t-1, 1-t)
// We fold ln2 into w: w'[c] = w[c]*ln2, accumulate acc += w'*max(lg2(x), K),
// negate once at the end.

#define B_DIM 512
#define H_DIM 8
#define C_DIM 8192
#define N_ELEM (B_DIM * C_DIM)        // 4194304
#define N4 (N_ELEM / 4)               // 1048576 float4 elements
#define C4 (C_DIM / 4)                // 2048
#define NTHREADS_TOTAL (N4 / 4)       // 262144 (each thread: 4 float4)
#define NBLOCKS (NTHREADS_TOTAL / 256)  // 1024

#define LOG2_CLAMP (-144.26950408889634f)   // -100 / ln2
#define LN2 (0.6931471805599453f)

__device__ float g_w4[C_DIM];         // per-class weight * ln2 / C, read as float4

// ---------------------------------------------------------------------------
// Kernel A: w'[c] = (ln2/C) * sum_h lam[h]*La[h,c]; also zero the output.
// ---------------------------------------------------------------------------
__global__ void multibce_weights_kernel(const float* __restrict__ La,
                                        const float* __restrict__ lam,
                                        float* __restrict__ out) {
    int c = blockIdx.x * blockDim.x + threadIdx.x;
    if (c < C_DIM) {
        float s = 0.0f;
#pragma unroll
        for (int h = 0; h < H_DIM; ++h) {
            s = fmaf(lam[h], La[h * C_DIM + c], s);
        }
        g_w4[c] = s * (LN2 / (float)C_DIM);
    }
    if (c == 0) out[0] = 0.0f;
}

// ---------------------------------------------------------------------------
// Kernel B: weighted BCE reduction. Each thread: 4 float4 at stride
// NTHREADS_TOTAL (multiple of C4), so same c4 for all 4 -> one w load.
// ---------------------------------------------------------------------------
__device__ __forceinline__ float term1(float p, float t) {
    // x = t ? p : 1-p   (exact for binary t)
    float x = fmaf(p, 2.0f * t - 1.0f, 1.0f - t);
    return fmaxf(__log2f(x), LOG2_CLAMP);
}

__global__ void __launch_bounds__(256)
multibce_reduce_kernel(const float4* __restrict__ yp,
                       const float4* __restrict__ yt,
                       float* __restrict__ out) {
    int tid = blockIdx.x * 256 + threadIdx.x;

    // Issue all loads up front for MLP.
    float4 p0 = yp[tid];
    float4 p1 = yp[tid + NTHREADS_TOTAL];
    float4 p2 = yp[tid + 2 * NTHREADS_TOTAL];
    float4 p3 = yp[tid + 3 * NTHREADS_TOTAL];
    float4 t0 = yt[tid];
    float4 t1 = yt[tid + NTHREADS_TOTAL];
    float4 t2 = yt[tid + 2 * NTHREADS_TOTAL];
    float4 t3 = yt[tid + 3 * NTHREADS_TOTAL];
    float4 w  = reinterpret_cast<const float4*>(g_w4)[tid & (C4 - 1)];

    float accx = 0.0f, accy = 0.0f, accz = 0.0f, accw = 0.0f;
    accx = fmaf(w.x, term1(p0.x, t0.x), accx);
    accy = fmaf(w.y, term1(p0.y, t0.y), accy);
    accz = fmaf(w.z, term1(p0.z, t0.z), accz);
    accw = fmaf(w.w, term1(p0.w, t0.w), accw);
    accx = fmaf(w.x, term1(p1.x, t1.x), accx);
    accy = fmaf(w.y, term1(p1.y, t1.y), accy);
    accz = fmaf(w.z, term1(p1.z, t1.z), accz);
    accw = fmaf(w.w, term1(p1.w, t1.w), accw);
    accx = fmaf(w.x, term1(p2.x, t2.x), accx);
    accy = fmaf(w.y, term1(p2.y, t2.y), accy);
    accz = fmaf(w.z, term1(p2.z, t2.z), accz);
    accw = fmaf(w.w, term1(p2.w, t2.w), accw);
    accx = fmaf(w.x, term1(p3.x, t3.x), accx);
    accy = fmaf(w.y, term1(p3.y, t3.y), accy);
    accz = fmaf(w.z, term1(p3.z, t3.z), accz);
    accw = fmaf(w.w, term1(p3.w, t3.w), accw);

    float acc = (accx + accy) + (accz + accw);

    // warp reduce
#pragma unroll
    for (int o = 16; o > 0; o >>= 1)
        acc += __shfl_xor_sync(0xFFFFFFFFu, acc, o);

    // block reduce
    __shared__ float smem[8];
    int lane = threadIdx.x & 31;
    int warp = threadIdx.x >> 5;
    if (lane == 0) smem[warp] = acc;
    __syncthreads();
    if (warp == 0) {
        acc = (lane < 8) ? smem[lane] : 0.0f;
#pragma unroll
        for (int o = 4; o > 0; o >>= 1)
            acc += __shfl_xor_sync(0xFFFFFFFFu, acc, o);
        if (lane == 0) atomicAdd(out, -acc);   // negate: loss = -sum
    }
}

// ---------------------------------------------------------------------------
extern "C" void kernel_launch(void* const* d_in, const int* in_sizes, int n_in,
                              void* d_out, int out_size) {
    const float* y_pred = (const float*)d_in[0];
    const float* y_true = (const float*)d_in[1];
    const float* La     = (const float*)d_in[2];
    const float* lam    = (const float*)d_in[3];
    float* out = (float*)d_out;

    multibce_weights_kernel<<<(C_DIM + 255) / 256, 256>>>(La, lam, out);
    multibce_reduce_kernel<<<NBLOCKS, 256>>>(
        (const float4*)y_pred, (const float4*)y_true, out);
}

// round 4
// speedup vs baseline: 1.2230x; 1.0540x over previous
#include <cuda_runtime.h>
#include <cuda_bf16.h>

// Problem: B=512, H=8, C=8192
//   loss = sum_{b,c} bce(y_pred[b,c], y_true[b,c]) * w[c]
//   w[c]  = (1/C) * sum_h lam[h] * La[h,c]     (La binary => masked terms are 0)
// y_true is binary, so bce(p,t) = -ln2 * max(lg2(t ? p : 1-p), -100/ln2).
// ln2 folded into w. Negate once at the end.
//
// Kernel B is sized for EXACTLY ONE WAVE: 512 blocks x 256 thr (regs capped to
// 64 via launch_bounds -> 4 blocks/SM -> 592 resident capacity >= 512), each
// thread handles 8 float4-pairs at stride 131072 (== 0 mod C4, so one w load).

#define B_DIM 512
#define H_DIM 8
#define C_DIM 8192
#define N_ELEM (B_DIM * C_DIM)        // 4194304
#define N4 (N_ELEM / 4)               // 1048576 float4 elements
#define C4 (C_DIM / 4)                // 2048
#define NT 131072                     // total threads in kernel B
#define NBLOCKS (NT / 256)            // 512
#define PAIRS 8                       // float4-pairs per thread (NT*PAIRS == N4)

#define LOG2_CLAMP (-144.26950408889634f)   // -100 / ln2
#define LN2 (0.6931471805599453f)

__device__ float g_w4[C_DIM];         // per-class weight * ln2 / C

// ---------------------------------------------------------------------------
// Kernel A: w'[c] = (ln2/C) * sum_h lam[h]*La[h,c]; also zero the output.
// ---------------------------------------------------------------------------
__global__ void multibce_weights_kernel(const float* __restrict__ La,
                                        const float* __restrict__ lam,
                                        float* __restrict__ out) {
    int c = blockIdx.x * blockDim.x + threadIdx.x;
    if (c < C_DIM) {
        float s = 0.0f;
#pragma unroll
        for (int h = 0; h < H_DIM; ++h) {
            s = fmaf(lam[h], La[h * C_DIM + c], s);
        }
        g_w4[c] = s * (LN2 / (float)C_DIM);
    }
    if (c == 0) out[0] = 0.0f;
}

// ---------------------------------------------------------------------------
// Kernel B: weighted BCE reduction, single wave.
// ---------------------------------------------------------------------------
__device__ __forceinline__ float term1(float p, float t) {
    // x = t ? p : 1-p   (exact for binary t)
    float x = fmaf(p, 2.0f * t - 1.0f, 1.0f - t);
    return fmaxf(__log2f(x), LOG2_CLAMP);
}

__global__ void __launch_bounds__(256, 4)
multibce_reduce_kernel(const float4* __restrict__ yp,
                       const float4* __restrict__ yt,
                       float* __restrict__ out) {
    int tid = blockIdx.x * 256 + threadIdx.x;

    float4 w = reinterpret_cast<const float4*>(g_w4)[tid & (C4 - 1)];

    float accx = 0.0f, accy = 0.0f, accz = 0.0f, accw = 0.0f;

    // 2 chunks x 4 pairs: 8 LDG.128 batched per chunk (MLP), regs bounded.
#pragma unroll 1
    for (int j = 0; j < PAIRS / 4; ++j) {
        int base = tid + j * 4 * NT;
        float4 p0 = yp[base];
        float4 p1 = yp[base + NT];
        float4 p2 = yp[base + 2 * NT];
        float4 p3 = yp[base + 3 * NT];
        float4 t0 = yt[base];
        float4 t1 = yt[base + NT];
        float4 t2 = yt[base + 2 * NT];
        float4 t3 = yt[base + 3 * NT];

        accx = fmaf(w.x, term1(p0.x, t0.x), accx);
        accy = fmaf(w.y, term1(p0.y, t0.y), accy);
        accz = fmaf(w.z, term1(p0.z, t0.z), accz);
        accw = fmaf(w.w, term1(p0.w, t0.w), accw);
        accx = fmaf(w.x, term1(p1.x, t1.x), accx);
        accy = fmaf(w.y, term1(p1.y, t1.y), accy);
        accz = fmaf(w.z, term1(p1.z, t1.z), accz);
        accw = fmaf(w.w, term1(p1.w, t1.w), accw);
        accx = fmaf(w.x, term1(p2.x, t2.x), accx);
        accy = fmaf(w.y, term1(p2.y, t2.y), accy);
        accz = fmaf(w.z, term1(p2.z, t2.z), accz);
        accw = fmaf(w.w, term1(p2.w, t2.w), accw);
        accx = fmaf(w.x, term1(p3.x, t3.x), accx);
        accy = fmaf(w.y, term1(p3.y, t3.y), accy);
        accz = fmaf(w.z, term1(p3.z, t3.z), accz);
        accw = fmaf(w.w, term1(p3.w, t3.w), accw);
    }

    float acc = (accx + accy) + (accz + accw);

    // warp reduce
#pragma unroll
    for (int o = 16; o > 0; o >>= 1)
        acc += __shfl_xor_sync(0xFFFFFFFFu, acc, o);

    // block reduce
    __shared__ float smem[8];
    int lane = threadIdx.x & 31;
    int warp = threadIdx.x >> 5;
    if (lane == 0) smem[warp] = acc;
    __syncthreads();
    if (warp == 0) {
        acc = (lane < 8) ? smem[lane] : 0.0f;
#pragma unroll
        for (int o = 4; o > 0; o >>= 1)
            acc += __shfl_xor_sync(0xFFFFFFFFu, acc, o);
        if (lane == 0) atomicAdd(out, -acc);   // negate: loss = -sum
    }
}

// ---------------------------------------------------------------------------
extern "C" void kernel_launch(void* const* d_in, const int* in_sizes, int n_in,
                              void* d_out, int out_size) {
    const float* y_pred = (const float*)d_in[0];
    const float* y_true = (const float*)d_in[1];
    const float* La     = (const float*)d_in[2];
    const float* lam    = (const float*)d_in[3];
    float* out = (float*)d_out;

    multibce_weights_kernel<<<(C_DIM + 255) / 256, 256>>>(La, lam, out);
    multibce_reduce_kernel<<<NBLOCKS, 256>>>(
        (const float4*)y_pred, (const float4*)y_true, out);
}